// round 3
// baseline (speedup 1.0000x reference)
#include <cuda_runtime.h>
#include <cuda_bf16.h>
#include <math.h>

// Problem constants
#define B_  2
#define S_  2048
#define H_  2048
#define NH_ 16
#define NKV_ 4
#define HD_ 128
#define QD_ (NH_*HD_)    // 2048
#define KD_ (NKV_*HD_)   // 512
#define MROWS_ (B_*S_)   // 4096

// Scratch (module-static device globals; allocation-free per harness rules)
__device__ float g_q[MROWS_*QD_];   // 32 MB
__device__ float g_k[MROWS_*KD_];   // 8 MB
__device__ float g_v[MROWS_*KD_];   // 8 MB
__device__ float g_o[MROWS_*QD_];   // 32 MB

// ---------------------------------------------------------------------------
// SGEMM: C[m,n] = sum_k A[m*K+k] * B[n*K+k]   (both operands K-contiguous, "NT")
// 128x128 tile, BK=16, 256 threads, 8x8 per thread.
// ---------------------------------------------------------------------------
__global__ __launch_bounds__(256, 2)
void sgemm_nt(const float* __restrict__ A, const float* __restrict__ B,
              float* __restrict__ C, int M, int N, int K)
{
    __shared__ float As[16][128];
    __shared__ float Bs[16][128];

    const int tid = threadIdx.x;
    const int bm = blockIdx.x * 128;
    const int bn = blockIdx.y * 128;
    const int tm = (tid >> 4) * 8;       // 0..120
    const int tn = (tid & 15) * 8;       // 0..120
    const int lrow = tid >> 2;           // 0..63
    const int lcol = (tid & 3) << 2;     // 0,4,8,12

    const float* Ap = A + (size_t)(bm + lrow) * K + lcol;
    const float* Bp = B + (size_t)(bn + lrow) * K + lcol;

    float acc[8][8];
#pragma unroll
    for (int i = 0; i < 8; i++)
#pragma unroll
        for (int j = 0; j < 8; j++) acc[i][j] = 0.f;

    for (int k0 = 0; k0 < K; k0 += 16) {
        float4 a0 = *(const float4*)(Ap);
        float4 a1 = *(const float4*)(Ap + (size_t)64 * K);
        float4 b0 = *(const float4*)(Bp);
        float4 b1 = *(const float4*)(Bp + (size_t)64 * K);
        Ap += 16; Bp += 16;

        __syncthreads();   // previous iteration's reads done before we overwrite
        As[lcol+0][lrow]    = a0.x; As[lcol+1][lrow]    = a0.y;
        As[lcol+2][lrow]    = a0.z; As[lcol+3][lrow]    = a0.w;
        As[lcol+0][lrow+64] = a1.x; As[lcol+1][lrow+64] = a1.y;
        As[lcol+2][lrow+64] = a1.z; As[lcol+3][lrow+64] = a1.w;
        Bs[lcol+0][lrow]    = b0.x; Bs[lcol+1][lrow]    = b0.y;
        Bs[lcol+2][lrow]    = b0.z; Bs[lcol+3][lrow]    = b0.w;
        Bs[lcol+0][lrow+64] = b1.x; Bs[lcol+1][lrow+64] = b1.y;
        Bs[lcol+2][lrow+64] = b1.z; Bs[lcol+3][lrow+64] = b1.w;
        __syncthreads();

#pragma unroll
        for (int k = 0; k < 16; k++) {
            float a[8], b[8];
            *(float4*)&a[0] = *(const float4*)&As[k][tm];
            *(float4*)&a[4] = *(const float4*)&As[k][tm + 4];
            *(float4*)&b[0] = *(const float4*)&Bs[k][tn];
            *(float4*)&b[4] = *(const float4*)&Bs[k][tn + 4];
#pragma unroll
            for (int i = 0; i < 8; i++)
#pragma unroll
                for (int j = 0; j < 8; j++)
                    acc[i][j] = fmaf(a[i], b[j], acc[i][j]);
        }
    }

#pragma unroll
    for (int i = 0; i < 8; i++) {
        float* Cp = C + (size_t)(bm + tm + i) * N + bn + tn;
        float4 c0 = make_float4(acc[i][0], acc[i][1], acc[i][2], acc[i][3]);
        float4 c1 = make_float4(acc[i][4], acc[i][5], acc[i][6], acc[i][7]);
        *(float4*)(Cp)     = c0;
        *(float4*)(Cp + 4) = c1;
    }
}

// ---------------------------------------------------------------------------
// RoPE (in-place on Q and K), double-precision angle math for accuracy.
// One thread per (buffer, b, s, head, pair i<64).
// ---------------------------------------------------------------------------
__global__ void rope_kernel(float* __restrict__ Q, float* __restrict__ Kv)
{
    const int NQ = B_ * S_ * NH_ * 64;
    const int NK = B_ * S_ * NKV_ * 64;
    int idx = blockIdx.x * blockDim.x + threadIdx.x;
    if (idx >= NQ + NK) return;

    float* base; int nheads; int li;
    if (idx < NQ) { base = Q;  nheads = NH_;  li = idx; }
    else          { base = Kv; nheads = NKV_; li = idx - NQ; }

    int i  = li & 63;
    int hh = (li >> 6) % nheads;
    int s  = (li / (64 * nheads)) % S_;
    int b  = li / (64 * nheads * S_);

    // inv_freq = 10000^(-i/64) ; freq = s * inv_freq   (double for phase accuracy)
    double inv = exp(-((double)i / 64.0) * 9.210340371976182736);  // ln(10000)
    double fr  = (double)s * inv;
    double sd, cd;
    sincos(fr, &sd, &cd);
    float c = (float)cd, sn = (float)sd;

    float* p = base + (((size_t)(b * S_ + s)) * nheads + hh) * HD_ + i;
    float x1 = p[0], x2 = p[64];
    p[0]  = x1 * c - x2 * sn;
    p[64] = x2 * c + x1 * sn;
}

// ---------------------------------------------------------------------------
// Flash attention, non-causal, d=128. 64 queries x 64 keys per tile.
// 256 threads: S-tile thread grid 16x16 (4x4 each, strided by 16);
// O accumulator 4 rows x 8 contiguous d-columns per thread.
// ---------------------------------------------------------------------------
#define AT_SMEM_FLOATS (64*128 + 64*132 + 64*128 + 64*68)

__global__ __launch_bounds__(256)
void attn_fwd(const float* __restrict__ Q, const float* __restrict__ K,
              const float* __restrict__ V, float* __restrict__ O)
{
    extern __shared__ float sm[];
    float* Qs = sm;                       // [64][128]
    float* Ks = Qs + 64 * 128;            // [64][132]  (padded: fragment loads)
    float* Vs = Ks + 64 * 132;            // [64][128]
    float* Ps = Vs + 64 * 128;            // [64][68]   (padded: STS pattern)

    const int tid = threadIdx.x;
    const int tm = tid >> 4;              // 0..15
    const int tn = tid & 15;              // 0..15
    const int qb = blockIdx.x;            // query tile
    const int h  = blockIdx.y;
    const int b  = blockIdx.z;
    const int kvh = h >> 2;               // n_rep = 4

    const float scale = 0.08838834764831845f; // 1/sqrt(128)

    const float* Qg = Q + ((size_t)(b * S_) + qb * 64) * QD_ + h * HD_;
    const float* Kg = K + (size_t)(b * S_) * KD_ + kvh * HD_;
    const float* Vg = V + (size_t)(b * S_) * KD_ + kvh * HD_;
    float*       Og = O + ((size_t)(b * S_) + qb * 64) * QD_ + h * HD_;

    // Load Q tile (softmax scale folded in)
    for (int i = tid; i < 64 * 32; i += 256) {
        int r = i >> 5, c4 = (i & 31) << 2;
        float4 q4 = *(const float4*)(Qg + (size_t)r * QD_ + c4);
        Qs[r * 128 + c4 + 0] = q4.x * scale;
        Qs[r * 128 + c4 + 1] = q4.y * scale;
        Qs[r * 128 + c4 + 2] = q4.z * scale;
        Qs[r * 128 + c4 + 3] = q4.w * scale;
    }

    float m_i[4], l_i[4], oa[4][8];
#pragma unroll
    for (int i = 0; i < 4; i++) {
        m_i[i] = -1e30f; l_i[i] = 0.f;
#pragma unroll
        for (int j = 0; j < 8; j++) oa[i][j] = 0.f;
    }

    for (int kt = 0; kt < S_ / 64; kt++) {
        __syncthreads();   // prior PV reads of Vs / Ps done
        const float* Kt = Kg + (size_t)(kt * 64) * KD_;
        const float* Vt = Vg + (size_t)(kt * 64) * KD_;
        for (int i = tid; i < 64 * 32; i += 256) {
            int r = i >> 5, c4 = (i & 31) << 2;
            float4 k4 = *(const float4*)(Kt + (size_t)r * KD_ + c4);
            float4 v4 = *(const float4*)(Vt + (size_t)r * KD_ + c4);
            Ks[r * 132 + c4 + 0] = k4.x; Ks[r * 132 + c4 + 1] = k4.y;
            Ks[r * 132 + c4 + 2] = k4.z; Ks[r * 132 + c4 + 3] = k4.w;
            Vs[r * 128 + c4 + 0] = v4.x; Vs[r * 128 + c4 + 1] = v4.y;
            Vs[r * 128 + c4 + 2] = v4.z; Vs[r * 128 + c4 + 3] = v4.w;
        }
        __syncthreads();

        // S = Q Kt^T  : rows tm+16i, cols tn+16j
        float s4[4][4];
#pragma unroll
        for (int i = 0; i < 4; i++)
#pragma unroll
            for (int j = 0; j < 4; j++) s4[i][j] = 0.f;

#pragma unroll 8
        for (int k = 0; k < HD_; k += 4) {
            float4 qf[4], kf[4];
#pragma unroll
            for (int i = 0; i < 4; i++)
                qf[i] = *(const float4*)&Qs[(tm + 16 * i) * 128 + k];
#pragma unroll
            for (int j = 0; j < 4; j++)
                kf[j] = *(const float4*)&Ks[(tn + 16 * j) * 132 + k];
#pragma unroll
            for (int i = 0; i < 4; i++)
#pragma unroll
                for (int j = 0; j < 4; j++) {
                    s4[i][j] = fmaf(qf[i].x, kf[j].x, s4[i][j]);
                    s4[i][j] = fmaf(qf[i].y, kf[j].y, s4[i][j]);
                    s4[i][j] = fmaf(qf[i].z, kf[j].z, s4[i][j]);
                    s4[i][j] = fmaf(qf[i].w, kf[j].w, s4[i][j]);
                }
        }

        // Online softmax update. Threads with the same tm (16 lanes, lane bits
        // 0-3 within each warp half) share rows -> xor-shuffle reduce.
#pragma unroll
        for (int i = 0; i < 4; i++) {
            float mx = fmaxf(fmaxf(s4[i][0], s4[i][1]), fmaxf(s4[i][2], s4[i][3]));
            mx = fmaxf(mx, __shfl_xor_sync(0xffffffffu, mx, 1));
            mx = fmaxf(mx, __shfl_xor_sync(0xffffffffu, mx, 2));
            mx = fmaxf(mx, __shfl_xor_sync(0xffffffffu, mx, 4));
            mx = fmaxf(mx, __shfl_xor_sync(0xffffffffu, mx, 8));
            float mnew = fmaxf(m_i[i], mx);
            float al = __expf(m_i[i] - mnew);
            m_i[i] = mnew;
            float rs = 0.f;
#pragma unroll
            for (int j = 0; j < 4; j++) {
                float p = __expf(s4[i][j] - mnew);
                s4[i][j] = p;
                rs += p;
            }
            rs += __shfl_xor_sync(0xffffffffu, rs, 1);
            rs += __shfl_xor_sync(0xffffffffu, rs, 2);
            rs += __shfl_xor_sync(0xffffffffu, rs, 4);
            rs += __shfl_xor_sync(0xffffffffu, rs, 8);
            l_i[i] = l_i[i] * al + rs;
#pragma unroll
            for (int j = 0; j < 8; j++) oa[i][j] *= al;
#pragma unroll
            for (int j = 0; j < 4; j++)
                Ps[(tm + 16 * i) * 68 + tn + 16 * j] = s4[i][j];
        }
        __syncthreads();

        // O += P @ V : rows tm+16i, cols tn*8 .. tn*8+7
#pragma unroll 8
        for (int k = 0; k < 64; k++) {
            float4 v0 = *(const float4*)&Vs[k * 128 + tn * 8];
            float4 v1 = *(const float4*)&Vs[k * 128 + tn * 8 + 4];
#pragma unroll
            for (int i = 0; i < 4; i++) {
                float p = Ps[(tm + 16 * i) * 68 + k];
                oa[i][0] = fmaf(p, v0.x, oa[i][0]);
                oa[i][1] = fmaf(p, v0.y, oa[i][1]);
                oa[i][2] = fmaf(p, v0.z, oa[i][2]);
                oa[i][3] = fmaf(p, v0.w, oa[i][3]);
                oa[i][4] = fmaf(p, v1.x, oa[i][4]);
                oa[i][5] = fmaf(p, v1.y, oa[i][5]);
                oa[i][6] = fmaf(p, v1.z, oa[i][6]);
                oa[i][7] = fmaf(p, v1.w, oa[i][7]);
            }
        }
    }

    // Epilogue: normalize and store
#pragma unroll
    for (int i = 0; i < 4; i++) {
        float inv = 1.0f / l_i[i];
        float4 o0 = make_float4(oa[i][0] * inv, oa[i][1] * inv,
                                oa[i][2] * inv, oa[i][3] * inv);
        float4 o1 = make_float4(oa[i][4] * inv, oa[i][5] * inv,
                                oa[i][6] * inv, oa[i][7] * inv);
        float* op = Og + (size_t)(tm + 16 * i) * QD_ + tn * 8;
        *(float4*)(op)     = o0;
        *(float4*)(op + 4) = o1;
    }
}

// ---------------------------------------------------------------------------
// Launch
// ---------------------------------------------------------------------------
extern "C" void kernel_launch(void* const* d_in, const int* in_sizes, int n_in,
                              void* d_out, int out_size)
{
    const float* X  = (const float*)d_in[0];
    const float* Wq = (const float*)d_in[1];
    const float* Wk = (const float*)d_in[2];
    const float* Wv = (const float*)d_in[3];
    const float* Wo = (const float*)d_in[4];
    float* out = (float*)d_out;

    float *q, *k, *v, *o;
    cudaGetSymbolAddress((void**)&q, g_q);
    cudaGetSymbolAddress((void**)&k, g_k);
    cudaGetSymbolAddress((void**)&v, g_v);
    cudaGetSymbolAddress((void**)&o, g_o);

    // QKV projections
    sgemm_nt<<<dim3(MROWS_/128, QD_/128), 256>>>(X, Wq, q, MROWS_, QD_, H_);
    sgemm_nt<<<dim3(MROWS_/128, KD_/128), 256>>>(X, Wk, k, MROWS_, KD_, H_);
    sgemm_nt<<<dim3(MROWS_/128, KD_/128), 256>>>(X, Wv, v, MROWS_, KD_, H_);

    // RoPE on q and k
    {
        int total = B_ * S_ * (NH_ + NKV_) * 64;
        rope_kernel<<<(total + 255) / 256, 256>>>(q, k);
    }

    // Flash attention
    {
        int smem = AT_SMEM_FLOATS * 4;
        cudaFuncSetAttribute(attn_fwd, cudaFuncAttributeMaxDynamicSharedMemorySize, smem);
        attn_fwd<<<dim3(S_/64, NH_, B_), 256, smem>>>(q, k, v, o);
    }

    // Output projection
    sgemm_nt<<<dim3(MROWS_/128, QD_/128), 256>>>(o, Wo, out, MROWS_, QD_, H_);
}

// round 11
// speedup vs baseline: 1.4519x; 1.4519x over previous
#include <cuda_runtime.h>
#include <cuda_bf16.h>
#include <math.h>
#include <cstdint>

// Problem constants (object-like numeric macros only)
#define B_  2
#define S_  2048
#define H_  2048
#define NH_ 16
#define NKV_ 4
#define HD_ 128
#define QD_ 2048
#define KD_ 512
#define MROWS_ 4096

// ---------------------------------------------------------------------------
// Scratch (device globals; allocation-free per harness rules)
// ---------------------------------------------------------------------------
__device__ float g_q[MROWS_*QD_];
__device__ float g_k[MROWS_*KD_];
__device__ float g_v[MROWS_*KD_];
__device__ float g_o[MROWS_*QD_];

__device__ __nv_bfloat16 g_xh[MROWS_*H_];
__device__ __nv_bfloat16 g_xl[MROWS_*H_];
__device__ __nv_bfloat16 g_wqh[QD_*H_];
__device__ __nv_bfloat16 g_wql[QD_*H_];
__device__ __nv_bfloat16 g_wkh[KD_*H_];
__device__ __nv_bfloat16 g_wkl[KD_*H_];
__device__ __nv_bfloat16 g_wvh[KD_*H_];
__device__ __nv_bfloat16 g_wvl[KD_*H_];
__device__ __nv_bfloat16 g_woh[QD_*H_];
__device__ __nv_bfloat16 g_wol[QD_*H_];
__device__ __nv_bfloat16 g_oh[MROWS_*QD_];
__device__ __nv_bfloat16 g_ol[MROWS_*QD_];

__device__ float g_rc[S_*64];
__device__ float g_rs[S_*64];

// ---------------------------------------------------------------------------
// Inline helpers (no function-like macros; plain-sm_103 instructions only)
// ---------------------------------------------------------------------------
__device__ __forceinline__ uint32_t s2u(const void* p) {
    uint32_t a;
    asm("{ .reg .u64 t; cvta.to.shared.u64 t, %1; cvt.u32.u64 %0, t; }"
        : "=r"(a) : "l"(p));
    return a;
}

__device__ __forceinline__ void ldsm4(uint32_t* r, uint32_t a) {
    asm volatile("ldmatrix.sync.aligned.m8n8.x4.shared.b16 {%0, %1, %2, %3}, [%4];"
                 : "=r"(r[0]), "=r"(r[1]), "=r"(r[2]), "=r"(r[3]) : "r"(a));
}

__device__ __forceinline__ void mma16816(float* c, const uint32_t* a, const uint32_t* b) {
    asm volatile(
        "mma.sync.aligned.m16n8k16.row.col.f32.bf16.bf16.f32 "
        "{%0, %1, %2, %3}, {%4, %5, %6, %7}, {%8, %9}, {%0, %1, %2, %3};"
        : "+f"(c[0]), "+f"(c[1]), "+f"(c[2]), "+f"(c[3])
        : "r"(a[0]), "r"(a[1]), "r"(a[2]), "r"(a[3]), "r"(b[0]), "r"(b[1]));
}

// ---------------------------------------------------------------------------
// Split fp32 -> bf16 hi/lo
// ---------------------------------------------------------------------------
__global__ void split_bf16(const float* __restrict__ x,
                           __nv_bfloat16* __restrict__ hi,
                           __nv_bfloat16* __restrict__ lo, int n)
{
    int i = (blockIdx.x * blockDim.x + threadIdx.x) * 4;
    if (i >= n) return;
    float4 v = *(const float4*)(x + i);
    __nv_bfloat16 h0 = __float2bfloat16(v.x);
    __nv_bfloat16 h1 = __float2bfloat16(v.y);
    __nv_bfloat16 h2 = __float2bfloat16(v.z);
    __nv_bfloat16 h3 = __float2bfloat16(v.w);
    __nv_bfloat16 l0 = __float2bfloat16(v.x - __bfloat162float(h0));
    __nv_bfloat16 l1 = __float2bfloat16(v.y - __bfloat162float(h1));
    __nv_bfloat16 l2 = __float2bfloat16(v.z - __bfloat162float(h2));
    __nv_bfloat16 l3 = __float2bfloat16(v.w - __bfloat162float(h3));
    __nv_bfloat162* hp = (__nv_bfloat162*)(hi + i);
    __nv_bfloat162* lp = (__nv_bfloat162*)(lo + i);
    __nv_bfloat162 p0; p0.x = h0; p0.y = h1; hp[0] = p0;
    __nv_bfloat162 p1; p1.x = h2; p1.y = h3; hp[1] = p1;
    __nv_bfloat162 p2; p2.x = l0; p2.y = l1; lp[0] = p2;
    __nv_bfloat162 p3; p3.x = l2; p3.y = l3; lp[1] = p3;
}

// ---------------------------------------------------------------------------
// Split-bf16 mma.sync GEMM: C[m,n] = sum_k A[m,k]*B[n,k]  (NT, ~fp32 accuracy)
// 128x128 block tile, BK=32, 8 warps (2x4), warp tile 64x32.
// Fragments via ldmatrix (smem pitch 40 bf16 -> conflict-free 8-row phases).
// Three passes hh + hl + lh accumulate into the same fp32 fragments.
// ---------------------------------------------------------------------------
__global__ __launch_bounds__(256)
void gemm_mma(const __nv_bfloat16* __restrict__ Ah, const __nv_bfloat16* __restrict__ Al,
              const __nv_bfloat16* __restrict__ Bh, const __nv_bfloat16* __restrict__ Bl,
              float* __restrict__ C, int M, int N, int K)
{
    __shared__ __nv_bfloat16 sAh[128 * 40];
    __shared__ __nv_bfloat16 sAl[128 * 40];
    __shared__ __nv_bfloat16 sBh[128 * 40];
    __shared__ __nv_bfloat16 sBl[128 * 40];

    const int tid  = threadIdx.x;
    const int lane = tid & 31;
    const int wid  = tid >> 5;
    const int wm   = wid >> 2;        // 0..1  -> m offset wm*64
    const int wn   = wid & 3;         // 0..3  -> n offset wn*32
    const int bm   = blockIdx.x * 128;
    const int bn   = blockIdx.y * 128;

    const uint32_t uAh = s2u(sAh);
    const uint32_t uAl = s2u(sAl);
    const uint32_t uBh = s2u(sBh);
    const uint32_t uBl = s2u(sBl);

    const __nv_bfloat16* pAh = Ah + (size_t)bm * K;
    const __nv_bfloat16* pAl = Al + (size_t)bm * K;
    const __nv_bfloat16* pBh = Bh + (size_t)bn * K;
    const __nv_bfloat16* pBl = Bl + (size_t)bn * K;

    float acc[4][4][4];
#pragma unroll
    for (int i = 0; i < 4; i++) {
#pragma unroll
        for (int j = 0; j < 4; j++) {
#pragma unroll
            for (int r = 0; r < 4; r++) acc[i][j][r] = 0.f;
        }
    }

    // ldmatrix address components (constant across iterations)
    const int g  = lane >> 3;         // matrix index 0..3
    const int lr = lane & 7;          // row within 8-row group
    // A groups: g0=(m0-7,k0-7) g1=(m8-15,k0-7) g2=(m0-7,k8-15) g3=(m8-15,k8-15)
    const int a_row = wm * 64 + (g & 1) * 8 + lr;
    const int a_col = (g >> 1) * 8;
    // B groups: g0=(n0-7,k0-7) g1=(n0-7,k8-15) g2=(n8-15,k0-7) g3=(n8-15,k8-15)
    const int b_row = wn * 32 + (g >> 1) * 8 + lr;
    const int b_col = (g & 1) * 8;

    const int nk = K >> 5;            // BK=32 iterations
    for (int c = 0; c < nk; c++) {
        __syncthreads();              // prior iteration's reads done
        // stage 128x32 bf16 of each of 4 arrays (each thread: 2 uint4 per array)
#pragma unroll
        for (int half = 0; half < 2; half++) {
            int lin = tid + half * 256;      // 0..511
            int r   = lin >> 2;              // 0..127
            int c8  = lin & 3;               // uint4 column
            size_t go = (size_t)r * K + (size_t)c * 32 + (size_t)c8 * 8;
            int so = r * 40 + c8 * 8;
            *(uint4*)(sAh + so) = *(const uint4*)(pAh + go);
            *(uint4*)(sAl + so) = *(const uint4*)(pAl + go);
            *(uint4*)(sBh + so) = *(const uint4*)(pBh + go);
            *(uint4*)(sBl + so) = *(const uint4*)(pBl + go);
        }
        __syncthreads();

#pragma unroll
        for (int ks = 0; ks < 2; ks++) {     // two k16 steps
            const int k0 = ks * 16;
            uint32_t afh[4][4], afl[4][4];
#pragma unroll
            for (int mt = 0; mt < 4; mt++) {
                uint32_t off = (uint32_t)((a_row + mt * 16) * 40 + k0 + a_col) * 2;
                ldsm4(afh[mt], uAh + off);
                ldsm4(afl[mt], uAl + off);
            }
#pragma unroll
            for (int np = 0; np < 2; np++) { // two n16 pairs -> 4 n8 tiles
                uint32_t bfh[4], bfl[4];
                uint32_t off = (uint32_t)((b_row + np * 16) * 40 + k0 + b_col) * 2;
                ldsm4(bfh, uBh + off);
                ldsm4(bfl, uBl + off);
#pragma unroll
                for (int mt = 0; mt < 4; mt++) {
#pragma unroll
                    for (int t2 = 0; t2 < 2; t2++) {
                        float* cc = acc[mt][np * 2 + t2];
                        mma16816(cc, afh[mt], bfh + t2 * 2);
                        mma16816(cc, afh[mt], bfl + t2 * 2);
                        mma16816(cc, afl[mt], bfh + t2 * 2);
                    }
                }
            }
        }
    }

    // Epilogue: c0,c1 = (row lane/4, col 2*(lane%4)+0,1); c2,c3 = row+8
    const int er = lane >> 2;
    const int ec = (lane & 3) * 2;
#pragma unroll
    for (int mt = 0; mt < 4; mt++) {
#pragma unroll
        for (int nt = 0; nt < 4; nt++) {
            int row = bm + wm * 64 + mt * 16 + er;
            int col = bn + wn * 32 + nt * 8 + ec;
            float2 v0; v0.x = acc[mt][nt][0]; v0.y = acc[mt][nt][1];
            float2 v1; v1.x = acc[mt][nt][2]; v1.y = acc[mt][nt][3];
            *(float2*)(C + (size_t)row * N + col)       = v0;
            *(float2*)(C + (size_t)(row + 8) * N + col) = v1;
        }
    }
}

// ---------------------------------------------------------------------------
// RoPE: DP table once (131K sincos), then fp32 apply
// ---------------------------------------------------------------------------
__global__ void rope_table_kernel()
{
    int i = blockIdx.x * blockDim.x + threadIdx.x;
    if (i >= S_ * 64) return;
    int s = i >> 6;
    int f = i & 63;
    double inv = exp(-((double)f / 64.0) * 9.210340371976182736);
    double fr = (double)s * inv;
    double sd, cd;
    sincos(fr, &sd, &cd);
    g_rc[i] = (float)cd;
    g_rs[i] = (float)sd;
}

__global__ void rope_apply_kernel(float* __restrict__ Q, float* __restrict__ Kv)
{
    const int NQ = B_ * S_ * NH_ * 64;
    const int NK = B_ * S_ * NKV_ * 64;
    int idx = blockIdx.x * blockDim.x + threadIdx.x;
    if (idx >= NQ + NK) return;

    float* base; int nh; int li;
    if (idx < NQ) { base = Q;  nh = NH_;  li = idx; }
    else          { base = Kv; nh = NKV_; li = idx - NQ; }

    int i  = li & 63;
    int hh = (li >> 6) % nh;
    int s  = (li / (64 * nh)) % S_;
    int b  = li / (64 * nh * S_);

    float c  = g_rc[(s << 6) | i];
    float sn = g_rs[(s << 6) | i];

    float* p = base + (((size_t)(b * S_ + s)) * nh + hh) * HD_ + i;
    float x1 = p[0];
    float x2 = p[64];
    p[0]  = x1 * c - x2 * sn;
    p[64] = x2 * c + x1 * sn;
}

// ---------------------------------------------------------------------------
// Flash attention (fp32): 64x64 tiles, d=128, 256 threads (R1-proven)
// smem floats: 64*128 + 64*132 + 64*128 + 64*68 = 29184 -> 116736 bytes
// ---------------------------------------------------------------------------
__global__ __launch_bounds__(256)
void attn_fwd(const float* __restrict__ Q, const float* __restrict__ K,
              const float* __restrict__ V, float* __restrict__ O)
{
    extern __shared__ float sm[];
    float* Qs = sm;                       // [64][128]
    float* Ks = Qs + 64 * 128;            // [64][132]
    float* Vs = Ks + 64 * 132;            // [64][128]
    float* Ps = Vs + 64 * 128;            // [64][68]

    const int tid = threadIdx.x;
    const int tm = tid >> 4;
    const int tn = tid & 15;
    const int qb = blockIdx.x;
    const int h  = blockIdx.y;
    const int b  = blockIdx.z;
    const int kvh = h >> 2;

    const float scale = 0.08838834764831845f;

    const float* Qg = Q + ((size_t)(b * S_) + qb * 64) * QD_ + h * HD_;
    const float* Kg = K + (size_t)(b * S_) * KD_ + kvh * HD_;
    const float* Vg = V + (size_t)(b * S_) * KD_ + kvh * HD_;
    float*       Og = O + ((size_t)(b * S_) + qb * 64) * QD_ + h * HD_;

    for (int i = tid; i < 64 * 32; i += 256) {
        int r = i >> 5;
        int c4 = (i & 31) << 2;
        float4 q4 = *(const float4*)(Qg + (size_t)r * QD_ + c4);
        Qs[r * 128 + c4 + 0] = q4.x * scale;
        Qs[r * 128 + c4 + 1] = q4.y * scale;
        Qs[r * 128 + c4 + 2] = q4.z * scale;
        Qs[r * 128 + c4 + 3] = q4.w * scale;
    }

    float m_i[4], l_i[4], oa[4][8];
#pragma unroll
    for (int i = 0; i < 4; i++) {
        m_i[i] = -1e30f;
        l_i[i] = 0.f;
#pragma unroll
        for (int j = 0; j < 8; j++) oa[i][j] = 0.f;
    }

    for (int kt = 0; kt < S_ / 64; kt++) {
        __syncthreads();
        const float* Kt = Kg + (size_t)(kt * 64) * KD_;
        const float* Vt = Vg + (size_t)(kt * 64) * KD_;
        for (int i = tid; i < 64 * 32; i += 256) {
            int r = i >> 5;
            int c4 = (i & 31) << 2;
            float4 k4 = *(const float4*)(Kt + (size_t)r * KD_ + c4);
            float4 v4 = *(const float4*)(Vt + (size_t)r * KD_ + c4);
            Ks[r * 132 + c4 + 0] = k4.x; Ks[r * 132 + c4 + 1] = k4.y;
            Ks[r * 132 + c4 + 2] = k4.z; Ks[r * 132 + c4 + 3] = k4.w;
            Vs[r * 128 + c4 + 0] = v4.x; Vs[r * 128 + c4 + 1] = v4.y;
            Vs[r * 128 + c4 + 2] = v4.z; Vs[r * 128 + c4 + 3] = v4.w;
        }
        __syncthreads();

        float s4[4][4];
#pragma unroll
        for (int i = 0; i < 4; i++) {
#pragma unroll
            for (int j = 0; j < 4; j++) s4[i][j] = 0.f;
        }

#pragma unroll 8
        for (int k = 0; k < HD_; k += 4) {
            float4 qf[4], kf[4];
#pragma unroll
            for (int i = 0; i < 4; i++) qf[i] = *(const float4*)&Qs[(tm + 16 * i) * 128 + k];
#pragma unroll
            for (int j = 0; j < 4; j++) kf[j] = *(const float4*)&Ks[(tn + 16 * j) * 132 + k];
#pragma unroll
            for (int i = 0; i < 4; i++) {
#pragma unroll
                for (int j = 0; j < 4; j++) {
                    s4[i][j] = fmaf(qf[i].x, kf[j].x, s4[i][j]);
                    s4[i][j] = fmaf(qf[i].y, kf[j].y, s4[i][j]);
                    s4[i][j] = fmaf(qf[i].z, kf[j].z, s4[i][j]);
                    s4[i][j] = fmaf(qf[i].w, kf[j].w, s4[i][j]);
                }
            }
        }

#pragma unroll
        for (int i = 0; i < 4; i++) {
            float mx = fmaxf(fmaxf(s4[i][0], s4[i][1]), fmaxf(s4[i][2], s4[i][3]));
            mx = fmaxf(mx, __shfl_xor_sync(0xffffffffu, mx, 1));
            mx = fmaxf(mx, __shfl_xor_sync(0xffffffffu, mx, 2));
            mx = fmaxf(mx, __shfl_xor_sync(0xffffffffu, mx, 4));
            mx = fmaxf(mx, __shfl_xor_sync(0xffffffffu, mx, 8));
            float mnew = fmaxf(m_i[i], mx);
            float al = __expf(m_i[i] - mnew);
            m_i[i] = mnew;
            float rs = 0.f;
#pragma unroll
            for (int j = 0; j < 4; j++) {
                float p = __expf(s4[i][j] - mnew);
                s4[i][j] = p;
                rs += p;
            }
            rs += __shfl_xor_sync(0xffffffffu, rs, 1);
            rs += __shfl_xor_sync(0xffffffffu, rs, 2);
            rs += __shfl_xor_sync(0xffffffffu, rs, 4);
            rs += __shfl_xor_sync(0xffffffffu, rs, 8);
            l_i[i] = l_i[i] * al + rs;
#pragma unroll
            for (int j = 0; j < 8; j++) oa[i][j] *= al;
#pragma unroll
            for (int j = 0; j < 4; j++) Ps[(tm + 16 * i) * 68 + tn + 16 * j] = s4[i][j];
        }
        __syncthreads();

#pragma unroll 8
        for (int k = 0; k < 64; k++) {
            float4 v0 = *(const float4*)&Vs[k * 128 + tn * 8];
            float4 v1 = *(const float4*)&Vs[k * 128 + tn * 8 + 4];
#pragma unroll
            for (int i = 0; i < 4; i++) {
                float p = Ps[(tm + 16 * i) * 68 + k];
                oa[i][0] = fmaf(p, v0.x, oa[i][0]);
                oa[i][1] = fmaf(p, v0.y, oa[i][1]);
                oa[i][2] = fmaf(p, v0.z, oa[i][2]);
                oa[i][3] = fmaf(p, v0.w, oa[i][3]);
                oa[i][4] = fmaf(p, v1.x, oa[i][4]);
                oa[i][5] = fmaf(p, v1.y, oa[i][5]);
                oa[i][6] = fmaf(p, v1.z, oa[i][6]);
                oa[i][7] = fmaf(p, v1.w, oa[i][7]);
            }
        }
    }

#pragma unroll
    for (int i = 0; i < 4; i++) {
        float inv = 1.0f / l_i[i];
        float4 o0 = make_float4(oa[i][0] * inv, oa[i][1] * inv, oa[i][2] * inv, oa[i][3] * inv);
        float4 o1 = make_float4(oa[i][4] * inv, oa[i][5] * inv, oa[i][6] * inv, oa[i][7] * inv);
        float* op = Og + (size_t)(tm + 16 * i) * QD_ + tn * 8;
        *(float4*)(op)     = o0;
        *(float4*)(op + 4) = o1;
    }
}

// ---------------------------------------------------------------------------
// Launch
// ---------------------------------------------------------------------------
extern "C" void kernel_launch(void* const* d_in, const int* in_sizes, int n_in,
                              void* d_out, int out_size)
{
    const float* X  = (const float*)d_in[0];
    const float* Wq = (const float*)d_in[1];
    const float* Wk = (const float*)d_in[2];
    const float* Wv = (const float*)d_in[3];
    const float* Wo = (const float*)d_in[4];
    float* out = (float*)d_out;

    float *q, *k, *v, *o;
    cudaGetSymbolAddress((void**)&q, g_q);
    cudaGetSymbolAddress((void**)&k, g_k);
    cudaGetSymbolAddress((void**)&v, g_v);
    cudaGetSymbolAddress((void**)&o, g_o);

    __nv_bfloat16 *xh, *xl, *wqh, *wql, *wkh, *wkl, *wvh, *wvl, *woh, *wol, *oh, *ol;
    cudaGetSymbolAddress((void**)&xh,  g_xh);
    cudaGetSymbolAddress((void**)&xl,  g_xl);
    cudaGetSymbolAddress((void**)&wqh, g_wqh);
    cudaGetSymbolAddress((void**)&wql, g_wql);
    cudaGetSymbolAddress((void**)&wkh, g_wkh);
    cudaGetSymbolAddress((void**)&wkl, g_wkl);
    cudaGetSymbolAddress((void**)&wvh, g_wvh);
    cudaGetSymbolAddress((void**)&wvl, g_wvl);
    cudaGetSymbolAddress((void**)&woh, g_woh);
    cudaGetSymbolAddress((void**)&wol, g_wol);
    cudaGetSymbolAddress((void**)&oh,  g_oh);
    cudaGetSymbolAddress((void**)&ol,  g_ol);

    int attn_smem = 116736;
    cudaFuncSetAttribute(attn_fwd, cudaFuncAttributeMaxDynamicSharedMemorySize, attn_smem);

    split_bf16<<<8192, 256>>>(X,  xh,  xl,  8388608);
    split_bf16<<<4096, 256>>>(Wq, wqh, wql, 4194304);
    split_bf16<<<1024, 256>>>(Wk, wkh, wkl, 1048576);
    split_bf16<<<1024, 256>>>(Wv, wvh, wvl, 1048576);
    split_bf16<<<4096, 256>>>(Wo, woh, wol, 4194304);

    gemm_mma<<<dim3(32, 16), 256>>>(xh, xl, wqh, wql, q, 4096, 2048, 2048);
    gemm_mma<<<dim3(32, 4),  256>>>(xh, xl, wkh, wkl, k, 4096, 512,  2048);
    gemm_mma<<<dim3(32, 4),  256>>>(xh, xl, wvh, wvl, v, 4096, 512,  2048);

    rope_table_kernel<<<512, 256>>>();
    rope_apply_kernel<<<20480, 256>>>(q, k);

    attn_fwd<<<dim3(32, 16, 2), 256, attn_smem>>>(q, k, v, o);

    split_bf16<<<8192, 256>>>(o, oh, ol, 8388608);
    gemm_mma<<<dim3(32, 16), 256>>>(oh, ol, woh, wol, out, 4096, 2048, 2048);
}

// round 15
// speedup vs baseline: 2.5694x; 1.7697x over previous
#include <cuda_runtime.h>
#include <cuda_bf16.h>
#include <math.h>
#include <cstdint>

// Problem constants (object-like numeric macros only)
#define B_  2
#define S_  2048
#define H_  2048
#define NH_ 16
#define NKV_ 4
#define HD_ 128
#define QD_ 2048
#define KD_ 512
#define MROWS_ 4096

// ---------------------------------------------------------------------------
// Scratch (device globals; allocation-free per harness rules)
// ---------------------------------------------------------------------------
__device__ float g_q[MROWS_*QD_];
__device__ float g_k[MROWS_*KD_];
__device__ float g_v[MROWS_*KD_];
__device__ float g_o[MROWS_*QD_];

__device__ __nv_bfloat16 g_xh[MROWS_*H_];
__device__ __nv_bfloat16 g_xl[MROWS_*H_];
__device__ __nv_bfloat16 g_wqh[QD_*H_];
__device__ __nv_bfloat16 g_wql[QD_*H_];
__device__ __nv_bfloat16 g_wkh[KD_*H_];
__device__ __nv_bfloat16 g_wkl[KD_*H_];
__device__ __nv_bfloat16 g_wvh[KD_*H_];
__device__ __nv_bfloat16 g_wvl[KD_*H_];
__device__ __nv_bfloat16 g_woh[QD_*H_];
__device__ __nv_bfloat16 g_wol[QD_*H_];
__device__ __nv_bfloat16 g_oh[MROWS_*QD_];
__device__ __nv_bfloat16 g_ol[MROWS_*QD_];

// attention operand splits (q scaled by 1/sqrt(d) before split)
__device__ __nv_bfloat16 g_qsh[MROWS_*QD_];
__device__ __nv_bfloat16 g_qsl[MROWS_*QD_];
__device__ __nv_bfloat16 g_ksh[MROWS_*KD_];
__device__ __nv_bfloat16 g_ksl[MROWS_*KD_];
__device__ __nv_bfloat16 g_vsh[MROWS_*KD_];
__device__ __nv_bfloat16 g_vsl[MROWS_*KD_];

__device__ float g_rc[S_*64];
__device__ float g_rs[S_*64];

// ---------------------------------------------------------------------------
// Inline helpers (no function-like macros; plain-sm_103 instructions only)
// ---------------------------------------------------------------------------
__device__ __forceinline__ uint32_t s2u(const void* p) {
    uint32_t a;
    asm("{ .reg .u64 t; cvta.to.shared.u64 t, %1; cvt.u32.u64 %0, t; }"
        : "=r"(a) : "l"(p));
    return a;
}

__device__ __forceinline__ void ldsm4(uint32_t* r, uint32_t a) {
    asm volatile("ldmatrix.sync.aligned.m8n8.x4.shared.b16 {%0, %1, %2, %3}, [%4];"
                 : "=r"(r[0]), "=r"(r[1]), "=r"(r[2]), "=r"(r[3]) : "r"(a));
}

__device__ __forceinline__ void ldsm4t(uint32_t* r, uint32_t a) {
    asm volatile("ldmatrix.sync.aligned.m8n8.x4.trans.shared.b16 {%0, %1, %2, %3}, [%4];"
                 : "=r"(r[0]), "=r"(r[1]), "=r"(r[2]), "=r"(r[3]) : "r"(a));
}

__device__ __forceinline__ void mma16816(float* c, const uint32_t* a, const uint32_t* b) {
    asm volatile(
        "mma.sync.aligned.m16n8k16.row.col.f32.bf16.bf16.f32 "
        "{%0, %1, %2, %3}, {%4, %5, %6, %7}, {%8, %9}, {%0, %1, %2, %3};"
        : "+f"(c[0]), "+f"(c[1]), "+f"(c[2]), "+f"(c[3])
        : "r"(a[0]), "r"(a[1]), "r"(a[2]), "r"(a[3]), "r"(b[0]), "r"(b[1]));
}

// pack two bf16 (lo -> bits[0:16), hi -> bits[16:32))
__device__ __forceinline__ uint32_t packbf(float lo, float hi) {
    uint32_t d;
    asm("cvt.rn.bf16x2.f32 %0, %1, %2;" : "=r"(d) : "f"(hi), "f"(lo));
    return d;
}

// ---------------------------------------------------------------------------
// Split fp32 -> bf16 hi/lo
// ---------------------------------------------------------------------------
__global__ void split_bf16(const float* __restrict__ x,
                           __nv_bfloat16* __restrict__ hi,
                           __nv_bfloat16* __restrict__ lo, int n)
{
    int i = (blockIdx.x * blockDim.x + threadIdx.x) * 4;
    if (i >= n) return;
    float4 v = *(const float4*)(x + i);
    __nv_bfloat16 h0 = __float2bfloat16(v.x);
    __nv_bfloat16 h1 = __float2bfloat16(v.y);
    __nv_bfloat16 h2 = __float2bfloat16(v.z);
    __nv_bfloat16 h3 = __float2bfloat16(v.w);
    __nv_bfloat16 l0 = __float2bfloat16(v.x - __bfloat162float(h0));
    __nv_bfloat16 l1 = __float2bfloat16(v.y - __bfloat162float(h1));
    __nv_bfloat16 l2 = __float2bfloat16(v.z - __bfloat162float(h2));
    __nv_bfloat16 l3 = __float2bfloat16(v.w - __bfloat162float(h3));
    __nv_bfloat162* hp = (__nv_bfloat162*)(hi + i);
    __nv_bfloat162* lp = (__nv_bfloat162*)(lo + i);
    __nv_bfloat162 p0; p0.x = h0; p0.y = h1; hp[0] = p0;
    __nv_bfloat162 p1; p1.x = h2; p1.y = h3; hp[1] = p1;
    __nv_bfloat162 p2; p2.x = l0; p2.y = l1; lp[0] = p2;
    __nv_bfloat162 p3; p3.x = l2; p3.y = l3; lp[1] = p3;
}

// ---------------------------------------------------------------------------
// Split-bf16 mma.sync GEMM (R11-proven): C[m,n] = sum_k A[m,k]*B[n,k]
// ---------------------------------------------------------------------------
__global__ __launch_bounds__(256)
void gemm_mma(const __nv_bfloat16* __restrict__ Ah, const __nv_bfloat16* __restrict__ Al,
              const __nv_bfloat16* __restrict__ Bh, const __nv_bfloat16* __restrict__ Bl,
              float* __restrict__ C, int M, int N, int K)
{
    __shared__ __nv_bfloat16 sAh[128 * 40];
    __shared__ __nv_bfloat16 sAl[128 * 40];
    __shared__ __nv_bfloat16 sBh[128 * 40];
    __shared__ __nv_bfloat16 sBl[128 * 40];

    const int tid  = threadIdx.x;
    const int lane = tid & 31;
    const int wid  = tid >> 5;
    const int wm   = wid >> 2;
    const int wn   = wid & 3;
    const int bm   = blockIdx.x * 128;
    const int bn   = blockIdx.y * 128;

    const uint32_t uAh = s2u(sAh);
    const uint32_t uAl = s2u(sAl);
    const uint32_t uBh = s2u(sBh);
    const uint32_t uBl = s2u(sBl);

    const __nv_bfloat16* pAh = Ah + (size_t)bm * K;
    const __nv_bfloat16* pAl = Al + (size_t)bm * K;
    const __nv_bfloat16* pBh = Bh + (size_t)bn * K;
    const __nv_bfloat16* pBl = Bl + (size_t)bn * K;

    float acc[4][4][4];
#pragma unroll
    for (int i = 0; i < 4; i++) {
#pragma unroll
        for (int j = 0; j < 4; j++) {
#pragma unroll
            for (int r = 0; r < 4; r++) acc[i][j][r] = 0.f;
        }
    }

    const int g  = lane >> 3;
    const int lr = lane & 7;
    const int a_row = wm * 64 + (g & 1) * 8 + lr;
    const int a_col = (g >> 1) * 8;
    const int b_row = wn * 32 + (g >> 1) * 8 + lr;
    const int b_col = (g & 1) * 8;

    const int nk = K >> 5;
    for (int c = 0; c < nk; c++) {
        __syncthreads();
#pragma unroll
        for (int half = 0; half < 2; half++) {
            int lin = tid + half * 256;
            int r   = lin >> 2;
            int c8  = lin & 3;
            size_t go = (size_t)r * K + (size_t)c * 32 + (size_t)c8 * 8;
            int so = r * 40 + c8 * 8;
            *(uint4*)(sAh + so) = *(const uint4*)(pAh + go);
            *(uint4*)(sAl + so) = *(const uint4*)(pAl + go);
            *(uint4*)(sBh + so) = *(const uint4*)(pBh + go);
            *(uint4*)(sBl + so) = *(const uint4*)(pBl + go);
        }
        __syncthreads();

#pragma unroll
        for (int ks = 0; ks < 2; ks++) {
            const int k0 = ks * 16;
            uint32_t afh[4][4], afl[4][4];
#pragma unroll
            for (int mt = 0; mt < 4; mt++) {
                uint32_t off = (uint32_t)((a_row + mt * 16) * 40 + k0 + a_col) * 2;
                ldsm4(afh[mt], uAh + off);
                ldsm4(afl[mt], uAl + off);
            }
#pragma unroll
            for (int np = 0; np < 2; np++) {
                uint32_t bfh[4], bfl[4];
                uint32_t off = (uint32_t)((b_row + np * 16) * 40 + k0 + b_col) * 2;
                ldsm4(bfh, uBh + off);
                ldsm4(bfl, uBl + off);
#pragma unroll
                for (int mt = 0; mt < 4; mt++) {
#pragma unroll
                    for (int t2 = 0; t2 < 2; t2++) {
                        float* cc = acc[mt][np * 2 + t2];
                        mma16816(cc, afh[mt], bfh + t2 * 2);
                        mma16816(cc, afh[mt], bfl + t2 * 2);
                        mma16816(cc, afl[mt], bfh + t2 * 2);
                    }
                }
            }
        }
    }

    const int er = lane >> 2;
    const int ec = (lane & 3) * 2;
#pragma unroll
    for (int mt = 0; mt < 4; mt++) {
#pragma unroll
        for (int nt = 0; nt < 4; nt++) {
            int row = bm + wm * 64 + mt * 16 + er;
            int col = bn + wn * 32 + nt * 8 + ec;
            float2 v0; v0.x = acc[mt][nt][0]; v0.y = acc[mt][nt][1];
            float2 v1; v1.x = acc[mt][nt][2]; v1.y = acc[mt][nt][3];
            *(float2*)(C + (size_t)row * N + col)       = v0;
            *(float2*)(C + (size_t)(row + 8) * N + col) = v1;
        }
    }
}

// ---------------------------------------------------------------------------
// RoPE: DP table once, then fp32 apply. Q additionally scaled by 1/sqrt(d).
// ---------------------------------------------------------------------------
__global__ void rope_table_kernel()
{
    int i = blockIdx.x * blockDim.x + threadIdx.x;
    if (i >= S_ * 64) return;
    int s = i >> 6;
    int f = i & 63;
    double inv = exp(-((double)f / 64.0) * 9.210340371976182736);
    double fr = (double)s * inv;
    double sd, cd;
    sincos(fr, &sd, &cd);
    g_rc[i] = (float)cd;
    g_rs[i] = (float)sd;
}

__global__ void rope_apply_kernel(float* __restrict__ Q, float* __restrict__ Kv)
{
    const int NQ = B_ * S_ * NH_ * 64;
    const int NK = B_ * S_ * NKV_ * 64;
    int idx = blockIdx.x * blockDim.x + threadIdx.x;
    if (idx >= NQ + NK) return;

    float* base; int nh; int li; float post;
    if (idx < NQ) { base = Q;  nh = NH_;  li = idx; post = 0.08838834764831845f; }
    else          { base = Kv; nh = NKV_; li = idx - NQ; post = 1.0f; }

    int i  = li & 63;
    int hh = (li >> 6) % nh;
    int s  = (li / (64 * nh)) % S_;
    int b  = li / (64 * nh * S_);

    float c  = g_rc[(s << 6) | i];
    float sn = g_rs[(s << 6) | i];

    float* p = base + (((size_t)(b * S_ + s)) * nh + hh) * HD_ + i;
    float x1 = p[0];
    float x2 = p[64];
    p[0]  = (x1 * c - x2 * sn) * post;
    p[64] = (x2 * c + x1 * sn) * post;
}

// ---------------------------------------------------------------------------
// Flash attention on HMMA (split-bf16, 3-pass): 128 queries/block, 64-key tiles.
// 8 warps, warp w owns query rows w*16..w*16+15 and full 64-key width
// (softmax row reductions stay inside a quad -> shfl only).
// smem: Q[128][136] hi+lo, K[64][136] hi+lo, V[64][136] hi+lo = 139264 B.
// ---------------------------------------------------------------------------
__global__ __launch_bounds__(256)
void attn_mma(const __nv_bfloat16* __restrict__ Qh, const __nv_bfloat16* __restrict__ Ql,
              const __nv_bfloat16* __restrict__ Kh, const __nv_bfloat16* __restrict__ Kl,
              const __nv_bfloat16* __restrict__ Vh, const __nv_bfloat16* __restrict__ Vl,
              float* __restrict__ O)
{
    extern __shared__ __nv_bfloat16 smb[];
    __nv_bfloat16* sQh = smb;                   // [128][136]
    __nv_bfloat16* sQl = sQh + 128 * 136;
    __nv_bfloat16* sKh = sQl + 128 * 136;       // [64][136]
    __nv_bfloat16* sKl = sKh + 64 * 136;
    __nv_bfloat16* sVh = sKl + 64 * 136;        // [64][136]
    __nv_bfloat16* sVl = sVh + 64 * 136;

    const int tid  = threadIdx.x;
    const int lane = tid & 31;
    const int w    = tid >> 5;
    const int qb   = blockIdx.x;
    const int h    = blockIdx.y;
    const int b    = blockIdx.z;
    const int kvh  = h >> 2;

    const uint32_t uQh = s2u(sQh), uQl = s2u(sQl);
    const uint32_t uKh = s2u(sKh), uKl = s2u(sKl);
    const uint32_t uVh = s2u(sVh), uVl = s2u(sVl);

    const __nv_bfloat16* gQh = Qh + ((size_t)(b * S_) + qb * 128) * QD_ + h * HD_;
    const __nv_bfloat16* gQl = Ql + ((size_t)(b * S_) + qb * 128) * QD_ + h * HD_;
    const __nv_bfloat16* gKh = Kh + (size_t)(b * S_) * KD_ + kvh * HD_;
    const __nv_bfloat16* gKl = Kl + (size_t)(b * S_) * KD_ + kvh * HD_;
    const __nv_bfloat16* gVh = Vh + (size_t)(b * S_) * KD_ + kvh * HD_;
    const __nv_bfloat16* gVl = Vl + (size_t)(b * S_) * KD_ + kvh * HD_;

    // stage Q (once)
    for (int i = tid; i < 2048; i += 256) {
        int r = i >> 4;
        int c8 = (i & 15) * 8;
        *(uint4*)(sQh + r * 136 + c8) = *(const uint4*)(gQh + (size_t)r * QD_ + c8);
        *(uint4*)(sQl + r * 136 + c8) = *(const uint4*)(gQl + (size_t)r * QD_ + c8);
    }

    const int g  = lane >> 3;
    const int lr = lane & 7;
    const int a_row  = w * 16 + (g & 1) * 8 + lr;   // Q rows
    const int a_col  = (g >> 1) * 8;
    const int b_row  = (g >> 1) * 8 + lr;           // K rows (per np: +np*16)
    const int b_col  = (g & 1) * 8;
    const int v_row  = (g & 1) * 8 + lr;            // V rows (per kk: +kk*16)
    const int v_col  = (g >> 1) * 8;                // V cols (per nn: +nn*16)

    float m0 = -1e30f, m1 = -1e30f, l0 = 0.f, l1 = 0.f;
    float oacc[16][4];
#pragma unroll
    for (int t = 0; t < 16; t++) {
#pragma unroll
        for (int j = 0; j < 4; j++) oacc[t][j] = 0.f;
    }

    for (int kt = 0; kt < 32; kt++) {
        __syncthreads();               // protect K/V smem (and Q on first iter)
        for (int i = tid; i < 1024; i += 256) {
            int r = i >> 4;
            int c8 = (i & 15) * 8;
            size_t go = (size_t)(kt * 64 + r) * KD_ + c8;
            int so = r * 136 + c8;
            *(uint4*)(sKh + so) = *(const uint4*)(gKh + go);
            *(uint4*)(sKl + so) = *(const uint4*)(gKl + go);
            *(uint4*)(sVh + so) = *(const uint4*)(gVh + go);
            *(uint4*)(sVl + so) = *(const uint4*)(gVl + go);
        }
        __syncthreads();

        // ---- S = Q K^T (3-pass split) ----
        float sacc[8][4];
#pragma unroll
        for (int t = 0; t < 8; t++) {
#pragma unroll
            for (int j = 0; j < 4; j++) sacc[t][j] = 0.f;
        }

#pragma unroll
        for (int kc = 0; kc < 8; kc++) {
            uint32_t ah[4], al[4];
            uint32_t aoff = (uint32_t)(a_row * 136 + kc * 16 + a_col) * 2;
            ldsm4(ah, uQh + aoff);
            ldsm4(al, uQl + aoff);
#pragma unroll
            for (int np = 0; np < 4; np++) {
                uint32_t bh4[4], bl4[4];
                uint32_t boff = (uint32_t)((np * 16 + b_row) * 136 + kc * 16 + b_col) * 2;
                ldsm4(bh4, uKh + boff);
                ldsm4(bl4, uKl + boff);
#pragma unroll
                for (int t2 = 0; t2 < 2; t2++) {
                    float* cc = sacc[np * 2 + t2];
                    mma16816(cc, ah, bh4 + t2 * 2);
                    mma16816(cc, ah, bl4 + t2 * 2);
                    mma16816(cc, al, bh4 + t2 * 2);
                }
            }
        }

        // ---- online softmax (rows er and er+8; reduce within quad) ----
        float mx0 = -1e30f, mx1 = -1e30f;
#pragma unroll
        for (int t = 0; t < 8; t++) {
            mx0 = fmaxf(mx0, fmaxf(sacc[t][0], sacc[t][1]));
            mx1 = fmaxf(mx1, fmaxf(sacc[t][2], sacc[t][3]));
        }
        mx0 = fmaxf(mx0, __shfl_xor_sync(0xffffffffu, mx0, 1));
        mx0 = fmaxf(mx0, __shfl_xor_sync(0xffffffffu, mx0, 2));
        mx1 = fmaxf(mx1, __shfl_xor_sync(0xffffffffu, mx1, 1));
        mx1 = fmaxf(mx1, __shfl_xor_sync(0xffffffffu, mx1, 2));

        float mn0 = fmaxf(m0, mx0);
        float mn1 = fmaxf(m1, mx1);
        float al0 = __expf(m0 - mn0);
        float al1 = __expf(m1 - mn1);
        m0 = mn0; m1 = mn1;

        float sum0 = 0.f, sum1 = 0.f;
#pragma unroll
        for (int t = 0; t < 8; t++) {
            float p0 = __expf(sacc[t][0] - m0);
            float p1 = __expf(sacc[t][1] - m0);
            float p2 = __expf(sacc[t][2] - m1);
            float p3 = __expf(sacc[t][3] - m1);
            sacc[t][0] = p0; sacc[t][1] = p1; sacc[t][2] = p2; sacc[t][3] = p3;
            sum0 += p0 + p1;
            sum1 += p2 + p3;
        }
        sum0 += __shfl_xor_sync(0xffffffffu, sum0, 1);
        sum0 += __shfl_xor_sync(0xffffffffu, sum0, 2);
        sum1 += __shfl_xor_sync(0xffffffffu, sum1, 1);
        sum1 += __shfl_xor_sync(0xffffffffu, sum1, 2);
        l0 = l0 * al0 + sum0;
        l1 = l1 * al1 + sum1;

#pragma unroll
        for (int t = 0; t < 16; t++) {
            oacc[t][0] *= al0; oacc[t][1] *= al0;
            oacc[t][2] *= al1; oacc[t][3] *= al1;
        }

        // ---- O += P V (3-pass split; P packed into A-frags in registers) ----
#pragma unroll
        for (int kk = 0; kk < 4; kk++) {
            float p00 = sacc[2 * kk][0],     p01 = sacc[2 * kk][1];
            float p02 = sacc[2 * kk][2],     p03 = sacc[2 * kk][3];
            float q00 = sacc[2 * kk + 1][0], q01 = sacc[2 * kk + 1][1];
            float q02 = sacc[2 * kk + 1][2], q03 = sacc[2 * kk + 1][3];
            uint32_t pa[4], pl[4];
            pa[0] = packbf(p00, p01);
            pa[1] = packbf(p02, p03);
            pa[2] = packbf(q00, q01);
            pa[3] = packbf(q02, q03);
            // lo residues vs rn-rounded hi (must match packbf rounding)
            float r00 = p00 - __bfloat162float(__float2bfloat16(p00));
            float r01 = p01 - __bfloat162float(__float2bfloat16(p01));
            float r02 = p02 - __bfloat162float(__float2bfloat16(p02));
            float r03 = p03 - __bfloat162float(__float2bfloat16(p03));
            float s00 = q00 - __bfloat162float(__float2bfloat16(q00));
            float s01 = q01 - __bfloat162float(__float2bfloat16(q01));
            float s02 = q02 - __bfloat162float(__float2bfloat16(q02));
            float s03 = q03 - __bfloat162float(__float2bfloat16(q03));
            pl[0] = packbf(r00, r01);
            pl[1] = packbf(r02, r03);
            pl[2] = packbf(s00, s01);
            pl[3] = packbf(s02, s03);

#pragma unroll
            for (int nn = 0; nn < 8; nn++) {
                uint32_t vh4[4], vl4[4];
                uint32_t voff = (uint32_t)((kk * 16 + v_row) * 136 + nn * 16 + v_col) * 2;
                ldsm4t(vh4, uVh + voff);
                ldsm4t(vl4, uVl + voff);
#pragma unroll
                for (int t2 = 0; t2 < 2; t2++) {
                    float* cc = oacc[nn * 2 + t2];
                    mma16816(cc, pa, vh4 + t2 * 2);
                    mma16816(cc, pa, vl4 + t2 * 2);
                    mma16816(cc, pl, vh4 + t2 * 2);
                }
            }
        }
    }

    // ---- epilogue: normalize, store ----
    const int er = lane >> 2;
    const int ec = (lane & 3) * 2;
    float inv0 = 1.0f / l0;
    float inv1 = 1.0f / l1;
    float* gO = O + ((size_t)(b * S_) + qb * 128 + w * 16) * QD_ + h * HD_;
#pragma unroll
    for (int t = 0; t < 16; t++) {
        int col = t * 8 + ec;
        float2 v0; v0.x = oacc[t][0] * inv0; v0.y = oacc[t][1] * inv0;
        float2 v1; v1.x = oacc[t][2] * inv1; v1.y = oacc[t][3] * inv1;
        *(float2*)(gO + (size_t)er * QD_ + col)       = v0;
        *(float2*)(gO + (size_t)(er + 8) * QD_ + col) = v1;
    }
}

// ---------------------------------------------------------------------------
// Launch
// ---------------------------------------------------------------------------
extern "C" void kernel_launch(void* const* d_in, const int* in_sizes, int n_in,
                              void* d_out, int out_size)
{
    const float* X  = (const float*)d_in[0];
    const float* Wq = (const float*)d_in[1];
    const float* Wk = (const float*)d_in[2];
    const float* Wv = (const float*)d_in[3];
    const float* Wo = (const float*)d_in[4];
    float* out = (float*)d_out;

    float *q, *k, *v, *o;
    cudaGetSymbolAddress((void**)&q, g_q);
    cudaGetSymbolAddress((void**)&k, g_k);
    cudaGetSymbolAddress((void**)&v, g_v);
    cudaGetSymbolAddress((void**)&o, g_o);

    __nv_bfloat16 *xh, *xl, *wqh, *wql, *wkh, *wkl, *wvh, *wvl, *woh, *wol, *oh, *ol;
    __nv_bfloat16 *qsh, *qsl, *ksh, *ksl, *vsh, *vsl;
    cudaGetSymbolAddress((void**)&xh,  g_xh);
    cudaGetSymbolAddress((void**)&xl,  g_xl);
    cudaGetSymbolAddress((void**)&wqh, g_wqh);
    cudaGetSymbolAddress((void**)&wql, g_wql);
    cudaGetSymbolAddress((void**)&wkh, g_wkh);
    cudaGetSymbolAddress((void**)&wkl, g_wkl);
    cudaGetSymbolAddress((void**)&wvh, g_wvh);
    cudaGetSymbolAddress((void**)&wvl, g_wvl);
    cudaGetSymbolAddress((void**)&woh, g_woh);
    cudaGetSymbolAddress((void**)&wol, g_wol);
    cudaGetSymbolAddress((void**)&oh,  g_oh);
    cudaGetSymbolAddress((void**)&ol,  g_ol);
    cudaGetSymbolAddress((void**)&qsh, g_qsh);
    cudaGetSymbolAddress((void**)&qsl, g_qsl);
    cudaGetSymbolAddress((void**)&ksh, g_ksh);
    cudaGetSymbolAddress((void**)&ksl, g_ksl);
    cudaGetSymbolAddress((void**)&vsh, g_vsh);
    cudaGetSymbolAddress((void**)&vsl, g_vsl);

    int attn_smem = 139264;
    cudaFuncSetAttribute(attn_mma, cudaFuncAttributeMaxDynamicSharedMemorySize, attn_smem);

    split_bf16<<<8192, 256>>>(X,  xh,  xl,  8388608);
    split_bf16<<<4096, 256>>>(Wq, wqh, wql, 4194304);
    split_bf16<<<1024, 256>>>(Wk, wkh, wkl, 1048576);
    split_bf16<<<1024, 256>>>(Wv, wvh, wvl, 1048576);
    split_bf16<<<4096, 256>>>(Wo, woh, wol, 4194304);

    gemm_mma<<<dim3(32, 16), 256>>>(xh, xl, wqh, wql, q, 4096, 2048, 2048);
    gemm_mma<<<dim3(32, 4),  256>>>(xh, xl, wkh, wkl, k, 4096, 512,  2048);
    gemm_mma<<<dim3(32, 4),  256>>>(xh, xl, wvh, wvl, v, 4096, 512,  2048);

    rope_table_kernel<<<512, 256>>>();
    rope_apply_kernel<<<20480, 256>>>(q, k);

    split_bf16<<<8192, 256>>>(q, qsh, qsl, 8388608);
    split_bf16<<<2048, 256>>>(k, ksh, ksl, 2097152);
    split_bf16<<<2048, 256>>>(v, vsh, vsl, 2097152);

    attn_mma<<<dim3(16, 16, 2), 256, attn_smem>>>(qsh, qsl, ksh, ksl, vsh, vsl, o);

    split_bf16<<<8192, 256>>>(o, oh, ol, 8388608);
    gemm_mma<<<dim3(32, 16), 256>>>(oh, ol, woh, wol, out, 4096, 2048, 2048);
}